// round 3
// baseline (speedup 1.0000x reference)
#include <cuda_runtime.h>
#include <math.h>

// 32x32 grid: packed = src_idx*8 + rot, or -1 if masked.
__device__ int d_packed[1024];

// Build the rotation table with EXACTLY the reference's arithmetic:
// theta = k*pi/4 (double), libm cos/sin (ulp-asymmetric values matter: for
// diagonal positions x==y the rotated coord is a cancellation whose tiny
// residue sign decides round(15.5 +/- eps)). rint == Python round (half-even).
// Sequential last-write-wins over ascending (idx,k) == atomicMax on idx*8+k.
// Trig hoisted: 16 libm calls total, rotations are pure DFMA.
__global__ void build_tables_kernel() {
    __shared__ double s_ct[8], s_st[8];
    const int tid = threadIdx.x;               // 1024 threads, 1 block
    if (tid < 8) {
        double theta = (double)tid * 3.141592653589793 / 4.0;
        s_ct[tid] = cos(theta);
        s_st[tid] = sin(theta);
    }
    d_packed[tid] = -1;
    __syncthreads();

    for (int pair = tid; pair < 136 * 8; pair += 1024) {
        int idx = pair >> 3;
        int k   = pair & 7;
        int i = 0;                              // decode idx -> (i, j)
        while ((i + 1) * (i + 2) / 2 <= idx) i++;
        int j = (31 - i) + (idx - i * (i + 1) / 2);

        double y = 15.5 - (double)i;
        double x = (double)j - 15.5;
        double ct = s_ct[k], st = s_st[k];
        double xn = ct * x - st * y;
        double yn = st * x + ct * y;
        int ir = (int)rint(15.5 - yn);
        int jr = (int)rint(15.5 + xn);
        ir = max(0, min(31, ir));
        jr = max(0, min(31, jr));
        atomicMax(&d_packed[ir * 32 + jr], pair);
    }
}

// ---------------------------------------------------------------------------
// Fused gather + broadcast-add, grid-strided over (position, batch-chunk)
// units for even SM load (1025-block version had 6-vs-7 blocks/SM imbalance).
// Unit = one float4 position x CHUNK batches; f computed once per unit.
// ---------------------------------------------------------------------------
#define P4      262400u            // float4 per batch row (1025*256)
#define CHUNK   8                  // batches per unit
#define NCHUNK  16                 // 128 / CHUNK
#define NUNITS  (P4 * NCHUNK)      // 4,198,400 units

__global__ void __launch_bounds__(256) add_posembed_kernel(
    const float4* __restrict__ x,
    const float4* __restrict__ P,     // (136, 8, 128) f32 = 136*256 float4
    const float4* __restrict__ cls,   // 128 f32 = 32 float4
    float4* __restrict__ out)
{
    const unsigned nthreads = gridDim.x * 256u;
    for (unsigned u = blockIdx.x * 256u + threadIdx.x; u < NUNITS; u += nthreads) {
        const unsigned c = u / P4;          // batch-chunk 0..15 (const divide)
        const unsigned p = u - c * P4;      // float4 position 0..262399
        const int t  = (int)(p >> 8);       // token 0..1024
        const int c4 = (int)(p & 255u);     // float4 within 1024 channels

        float4 f;
        if (t == 0) {
            f = cls[c4 & 31];               // CLS tiled across 8 groups
        } else {
            const int packed = d_packed[t - 1];
            if (packed < 0) {
                f = make_float4(0.f, 0.f, 0.f, 0.f);
            } else {
                const int group = ((c4 >> 5) - (packed & 7)) & 7;
                f = P[(packed >> 3) * 256 + group * 32 + (c4 & 31)];
            }
        }

        size_t off = (size_t)c * (CHUNK * (size_t)P4) + p;
#pragma unroll
        for (int b = 0; b < CHUNK; b++) {
            float4 v = __ldcs(x + off);
            v.x += f.x; v.y += f.y; v.z += f.z; v.w += f.w;
            __stcs(out + off, v);
            off += P4;
        }
    }
}

extern "C" void kernel_launch(void* const* d_in, const int* in_sizes, int n_in,
                              void* d_out, int out_size) {
    const float4* x   = (const float4*)d_in[0];  // (128, 1025, 1024) f32
    const float4* P   = (const float4*)d_in[1];  // (1, 136, 1024) f32
    const float4* cls = (const float4*)d_in[2];  // (1, 1, 128) f32
    float4* out = (float4*)d_out;

    build_tables_kernel<<<1, 1024>>>();
    add_posembed_kernel<<<148 * 8, 256>>>(x, P, cls, out);
}

// round 4
// speedup vs baseline: 1.0989x; 1.0989x over previous
#include <cuda_runtime.h>

// ---------------------------------------------------------------------------
// Compile-time rotation table, bit-exact vs the reference.
// The trig doubles below are the correctly-rounded cos/sin of k*pi_d/4
// (pi_d = double(pi); k*pi_d/4 is EXACT in double for k=0..7). These are the
// well-known asymmetric libm values (e.g. cos(pi/4)=...476, sin(pi/4)=...475);
// the 1-ulp asymmetries decide the sign of the cancellation residue on
// diagonal positions (x==y) and hence round(15.5 -/+ eps) = 15 vs 16.
// R1 (device libm, rel_err 0.0) proved libm == reference table.
// Expression shape matches Python exactly: fl(fl(ct*x) - fl(st*y)).
// ---------------------------------------------------------------------------
struct Table { int v[1024]; };

constexpr int iround(double v) {
    // == rint here: the only exact .5 value reachable is 15.5 (diagonal
    // cancellation -> residue exactly 0), and +0.5 gives 16 = half-even.
    return v >= 0.0 ? (int)(v + 0.5) : -(int)(0.5 - v);
}
constexpr int iclamp31(int v) { return v < 0 ? 0 : (v > 31 ? 31 : v); }

constexpr Table make_table() {
    Table t{};
    for (int c = 0; c < 1024; c++) t.v[c] = -1;
    // cos(k*pi/4), sin(k*pi/4) — exact libm doubles:
    const double ct[8] = { 1.0,                     0.7071067811865476,
                           6.123233995736766e-17,  -0.7071067811865475,
                          -1.0,                    -0.7071067811865477,
                          -1.8369701987210297e-16,  0.7071067811865474 };
    const double st[8] = { 0.0,                     0.7071067811865475,
                           1.0,                     0.7071067811865476,
                           1.2246467991473532e-16, -0.7071067811865475,
                          -1.0,                    -0.7071067811865477 };
    int idx = 0;
    for (int i = 0; i < 16; i++) {
        for (int j = 31 - i; j < 32; j++) {       // octant: angle in [0, pi/4]
            double y = 15.5 - (double)i;
            double x = (double)j - 15.5;
            for (int k = 0; k < 8; k++) {
                double xn = ct[k] * x - st[k] * y;
                double yn = st[k] * x + ct[k] * y;
                int ir = iclamp31(iround(15.5 - yn));
                int jr = iclamp31(iround(15.5 + xn));
                t.v[ir * 32 + jr] = idx * 8 + k;   // last write wins
            }
            idx++;
        }
    }
    return t;
}

__constant__ constexpr Table TBL = make_table();

// ---------------------------------------------------------------------------
// Fused gather + broadcast-add, grid-strided over (position, batch-chunk).
// Inner loop split into load-all / store-all so 8 LDG.128 are front-batched
// (high MLP) instead of serialized ldcs->add->stcs chains (R3: regs=30).
// ---------------------------------------------------------------------------
#define P4      262400u            // float4 per batch row (1025*256)
#define CHUNK   8                  // batches per unit
#define NCHUNK  16                 // 128 / CHUNK
#define NUNITS  (P4 * NCHUNK)

__global__ void __launch_bounds__(256) add_posembed_kernel(
    const float4* __restrict__ x,
    const float4* __restrict__ P,     // (136, 8, 128) f32 = 136*256 float4
    const float4* __restrict__ cls,   // 128 f32 = 32 float4
    float4* __restrict__ out)
{
    const unsigned nthreads = gridDim.x * 256u;
    for (unsigned u = blockIdx.x * 256u + threadIdx.x; u < NUNITS; u += nthreads) {
        const unsigned c = u / P4;          // batch-chunk 0..15
        const unsigned p = u - c * P4;      // float4 position 0..262399
        const int t  = (int)(p >> 8);       // token 0..1024
        const int c4 = (int)(p & 255u);     // float4 within 1024 channels

        float4 f;
        if (t == 0) {
            f = cls[c4 & 31];               // CLS tiled across 8 groups
        } else {
            const int packed = TBL.v[t - 1];
            if (packed < 0) {
                f = make_float4(0.f, 0.f, 0.f, 0.f);
            } else {
                const int group = ((c4 >> 5) - (packed & 7)) & 7;
                f = P[(packed >> 3) * 256 + group * 32 + (c4 & 31)];
            }
        }

        const size_t base = (size_t)c * (CHUNK * (size_t)P4) + p;
        float4 r[CHUNK];
#pragma unroll
        for (int b = 0; b < CHUNK; b++)
            r[b] = __ldcs(x + base + (size_t)b * P4);
#pragma unroll
        for (int b = 0; b < CHUNK; b++) {
            r[b].x += f.x; r[b].y += f.y; r[b].z += f.z; r[b].w += f.w;
            __stcs(out + base + (size_t)b * P4, r[b]);
        }
    }
}

extern "C" void kernel_launch(void* const* d_in, const int* in_sizes, int n_in,
                              void* d_out, int out_size) {
    const float4* x   = (const float4*)d_in[0];  // (128, 1025, 1024) f32
    const float4* P   = (const float4*)d_in[1];  // (1, 136, 1024) f32
    const float4* cls = (const float4*)d_in[2];  // (1, 1, 128) f32
    float4* out = (float4*)d_out;

    add_posembed_kernel<<<148 * 8, 256>>>(x, P, cls, out);
}